// round 9
// baseline (speedup 1.0000x reference)
#include <cuda_runtime.h>
#include <cstdint>

// Problem shapes (fixed by the dataset problem)
#define B 32
#define F 1024
#define S 2048
#define TOPK 16

#define ROWCH 8                      // row chunks per batch
#define ROWS_PER_CHUNK (S / ROWCH)   // 256
#define COLCH 2                      // column chunks (256 float4 each)
#define THREADS 256

#define NCOLSUM 128                          // persistent colsum blocks
#define UNITS (B * ROWCH * COLCH)            // 512 (batch,part) units
#define NTOPK B                              // 32  (one per batch)
#define GATHER_PER_B 4                       // 4 gather blocks per batch
#define NGATHER (B * GATHER_PER_B)           // 128
#define NBLOCKS (NCOLSUM + NTOPK + NGATHER)  // 288

// Scratch (no allocation allowed in kernel_launch)
__device__ float g_partials[ROWCH * B * S];   // 2 MB
__device__ int   g_topk[B * TOPK];
__device__ int   g_cnt[B];                    // colsum units done per batch
__device__ int   g_flag[B];                   // topk done per batch

// ---------------------------------------------------------------------------
// Reset sync state so every graph replay starts identically (deterministic).
// ---------------------------------------------------------------------------
__global__ void reset_kernel() {
    if (threadIdx.x < B) { g_cnt[threadIdx.x] = 0; g_flag[threadIdx.x] = 0; }
}

// ---------------------------------------------------------------------------
// Fused persistent kernel, block-role specialized:
//   [0, 128)   colsum  — grid-stride over units ordered batch-major, so
//                        batches complete at staggered times.
//   [128, 160) topk    — per batch: spin on counter, reduce partials (L2-hot),
//                        16x iterative argmax, publish flag.
//   [160, 288) gather  — per batch: spin on flag, gather 16 columns per f-row.
// Colsum blocks never wait -> no circular dependency -> no deadlock.
// ---------------------------------------------------------------------------
__global__ void __launch_bounds__(THREADS) fused_kernel(const float* __restrict__ x,
                                                        const float* __restrict__ w,
                                                        float* __restrict__ out) {
    const int bid = blockIdx.x;
    const int t   = threadIdx.x;

    if (bid < NCOLSUM) {
        // ---- colsum role ----
        const int str = S / 4;                // float4 stride per row = 512
        for (int u = bid; u < UNITS; u += NCOLSUM) {
            const int b    = u >> 4;          // batch (units batch-major)
            const int part = u & 15;
            const int cc   = part & 1;        // column chunk
            const int rc   = part >> 1;       // row chunk
            const int col4 = cc * THREADS + t;

            const float4* __restrict__ p =
                reinterpret_cast<const float4*>(
                    w + (size_t)b * S * S + (size_t)(rc * ROWS_PER_CHUNK) * S) + col4;

            float4 a0 = make_float4(0.f, 0.f, 0.f, 0.f);
            float4 a1 = a0, a2 = a0, a3 = a0;

            #pragma unroll 4
            for (int r = 0; r < ROWS_PER_CHUNK; r += 4) {
                float4 v0 = __ldcs(p + 0 * str);
                float4 v1 = __ldcs(p + 1 * str);
                float4 v2 = __ldcs(p + 2 * str);
                float4 v3 = __ldcs(p + 3 * str);
                p += 4 * str;
                a0.x += v0.x; a0.y += v0.y; a0.z += v0.z; a0.w += v0.w;
                a1.x += v1.x; a1.y += v1.y; a1.z += v1.z; a1.w += v1.w;
                a2.x += v2.x; a2.y += v2.y; a2.z += v2.z; a2.w += v2.w;
                a3.x += v3.x; a3.y += v3.y; a3.z += v3.z; a3.w += v3.w;
            }

            float4 s;
            s.x = (a0.x + a1.x) + (a2.x + a3.x);
            s.y = (a0.y + a1.y) + (a2.y + a3.y);
            s.z = (a0.z + a1.z) + (a2.z + a3.z);
            s.w = (a0.w + a1.w) + (a2.w + a3.w);

            reinterpret_cast<float4*>(
                g_partials + ((size_t)rc * B + b) * S)[col4] = s;

            __threadfence();                 // release: partials before counter
            __syncthreads();                 // all threads' fences done
            if (t == 0) atomicAdd(&g_cnt[b], 1);
        }

    } else if (bid < NCOLSUM + NTOPK) {
        // ---- topk role (one block per batch) ----
        __shared__ unsigned long long s_warp[THREADS / 32];
        __shared__ unsigned long long s_best;

        const int b    = bid - NCOLSUM;
        const int lane = t & 31;
        const int wid  = t >> 5;

        if (t == 0) {
            while (atomicAdd(&g_cnt[b], 0) < ROWCH * COLCH) __nanosleep(128);
        }
        __syncthreads();
        __threadfence();                     // acquire: see partials

        // Fused reduce of the 8 row-chunk partials into registers (L2-hot).
        float v[8];
        #pragma unroll
        for (int i = 0; i < 8; i++) {
            const int c = i * THREADS + t;
            float s = 0.f;
            #pragma unroll
            for (int rc = 0; rc < ROWCH; rc++)
                s += g_partials[((size_t)rc * B + b) * S + c];
            v[i] = s;
        }

        // 16x iterative argmax. Key packing -> descending value, lowest-index
        // tie-break: matches lax.top_k (index order feeds take_along_axis).
        for (int it = 0; it < TOPK; it++) {
            unsigned long long best = 0ull;
            #pragma unroll
            for (int i = 0; i < 8; i++) {
                unsigned fb = __float_as_uint(v[i]);
                fb = (fb & 0x80000000u) ? ~fb : (fb | 0x80000000u);
                unsigned long long key =
                    ((unsigned long long)fb << 32) |
                    (unsigned)(0xFFFFFFFFu - (unsigned)(i * THREADS + t));
                best = (key > best) ? key : best;
            }
            #pragma unroll
            for (int off = 16; off > 0; off >>= 1) {
                unsigned long long o = __shfl_xor_sync(0xFFFFFFFFu, best, off);
                best = (o > best) ? o : best;
            }
            if (lane == 0) s_warp[wid] = best;
            __syncthreads();
            if (t == 0) {
                unsigned long long m = s_warp[0];
                #pragma unroll
                for (int j = 1; j < THREADS / 32; j++)
                    m = (s_warp[j] > m) ? s_warp[j] : m;
                s_best = m;
                g_topk[b * TOPK + it] =
                    (int)(0xFFFFFFFFu - (unsigned)(m & 0xFFFFFFFFull));
            }
            __syncthreads();
            const int c = (int)(0xFFFFFFFFu - (unsigned)(s_best & 0xFFFFFFFFull));
            if ((c & (THREADS - 1)) == t)
                v[c >> 8] = -3.402823466e38f;
        }

        __threadfence();                     // release: g_topk before flag
        __syncthreads();
        if (t == 0) atomicExch(&g_flag[b], 1);

    } else {
        // ---- gather role (4 blocks per batch) ----
        __shared__ int s_idx[TOPK];

        const int g     = bid - (NCOLSUM + NTOPK);
        const int b     = g >> 2;
        const int fpart = g & 3;
        const int f     = fpart * THREADS + t;      // 0..F-1

        if (t == 0) {
            while (atomicAdd(&g_flag[b], 0) == 0) __nanosleep(128);
        }
        __syncthreads();
        __threadfence();                     // acquire: see g_topk
        if (t < TOPK) s_idx[t] = g_topk[b * TOPK + t];
        __syncthreads();

        const float* __restrict__ row = x + ((size_t)b * F + f) * S;

        float r[TOPK];
        #pragma unroll
        for (int k = 0; k < TOPK; k++)
            r[k] = __ldg(row + s_idx[k]);

        float4* __restrict__ o4 =
            reinterpret_cast<float4*>(out + ((size_t)b * F + f) * TOPK);
        #pragma unroll
        for (int j = 0; j < TOPK / 4; j++)
            o4[j] = make_float4(r[4 * j], r[4 * j + 1], r[4 * j + 2], r[4 * j + 3]);
    }
}

// ---------------------------------------------------------------------------
extern "C" void kernel_launch(void* const* d_in, const int* in_sizes, int n_in,
                              void* d_out, int out_size) {
    const float* x = (const float*)d_in[0];   // [B, F, S]
    const float* w = (const float*)d_in[1];   // [B, S, S]
    float* out = (float*)d_out;               // [B, F, TOPK]

    (void)in_sizes; (void)n_in; (void)out_size;

    reset_kernel<<<1, THREADS>>>();
    fused_kernel<<<NBLOCKS, THREADS>>>(x, w, out);
}

// round 10
// speedup vs baseline: 1.7917x; 1.7917x over previous
#include <cuda_runtime.h>
#include <cstdint>

// Problem shapes (fixed by the dataset problem)
#define B 32
#define F 1024
#define S 2048
#define TOPK 16

#define ROWCH 8                      // row chunks per batch
#define ROWS_PER_CHUNK (S / ROWCH)   // 256
#define COLCH 2                      // column chunks (256 float4 each)
#define THREADS 256

#define NCOLSUM (B * ROWCH * COLCH)          // 512: ONE unit per block (proven config)
#define NTOPK B                              // 32  (one per batch)
#define GATHER_PER_B 4                       // 4 gather blocks per batch
#define NGATHER (B * GATHER_PER_B)           // 128
#define NBLOCKS (NCOLSUM + NTOPK + NGATHER)  // 672  (< 148 SMs * 6 blocks -> all wave-1)

// Scratch (no allocation allowed in kernel_launch)
__device__ float g_partials[ROWCH * B * S];   // 2 MB
__device__ int   g_topk[B * TOPK];
__device__ int   g_cnt[B];                    // colsum units done per batch
__device__ int   g_flag[B];                   // topk done per batch

// ---------------------------------------------------------------------------
// Reset sync state so every graph replay starts identically (deterministic).
// ---------------------------------------------------------------------------
__global__ void reset_kernel() {
    if (threadIdx.x < B) { g_cnt[threadIdx.x] = 0; g_flag[threadIdx.x] = 0; }
}

// ---------------------------------------------------------------------------
// Fused kernel, block-role specialized. All 672 blocks are wave-1 resident
// (launch_bounds caps regs at 42 -> 6 blocks/SM -> 888 slots), so spinners
// can never starve producers -> no deadlock.
//   [0, 512)   colsum — one (batch, rowchunk, colchunk) unit per block,
//                       identical inner loop to the 6.6 TB/s standalone kernel.
//   [512, 544) topk   — per batch: spin on counter, reduce 8 partials (L2-hot),
//                       16x iterative argmax, publish flag.
//   [544, 672) gather — per batch: spin on flag, 16 loads per f-row.
// ---------------------------------------------------------------------------
__global__ void __launch_bounds__(THREADS, 6) fused_kernel(const float* __restrict__ x,
                                                           const float* __restrict__ w,
                                                           float* __restrict__ out) {
    const int bid = blockIdx.x;
    const int t   = threadIdx.x;

    if (bid < NCOLSUM) {
        // ---- colsum role: exactly one unit ----
        const int b    = bid >> 4;            // units batch-major
        const int part = bid & 15;
        const int cc   = part & 1;            // column chunk
        const int rc   = part >> 1;           // row chunk
        const int col4 = cc * THREADS + t;    // float4 column index
        const int str  = S / 4;               // float4 stride per row = 512

        const float4* __restrict__ p =
            reinterpret_cast<const float4*>(
                w + (size_t)b * S * S + (size_t)(rc * ROWS_PER_CHUNK) * S) + col4;

        float4 a0 = make_float4(0.f, 0.f, 0.f, 0.f);
        float4 a1 = a0, a2 = a0, a3 = a0;

        #pragma unroll 4
        for (int r = 0; r < ROWS_PER_CHUNK; r += 4) {
            float4 v0 = __ldcs(p + 0 * str);
            float4 v1 = __ldcs(p + 1 * str);
            float4 v2 = __ldcs(p + 2 * str);
            float4 v3 = __ldcs(p + 3 * str);
            p += 4 * str;
            a0.x += v0.x; a0.y += v0.y; a0.z += v0.z; a0.w += v0.w;
            a1.x += v1.x; a1.y += v1.y; a1.z += v1.z; a1.w += v1.w;
            a2.x += v2.x; a2.y += v2.y; a2.z += v2.z; a2.w += v2.w;
            a3.x += v3.x; a3.y += v3.y; a3.z += v3.z; a3.w += v3.w;
        }

        float4 s;
        s.x = (a0.x + a1.x) + (a2.x + a3.x);
        s.y = (a0.y + a1.y) + (a2.y + a3.y);
        s.z = (a0.z + a1.z) + (a2.z + a3.z);
        s.w = (a0.w + a1.w) + (a2.w + a3.w);

        reinterpret_cast<float4*>(g_partials + ((size_t)rc * B + b) * S)[col4] = s;

        __threadfence();                      // release: partials before counter
        __syncthreads();                      // all threads' stores+fences done
        if (t == 0) atomicAdd(&g_cnt[b], 1);

    } else if (bid < NCOLSUM + NTOPK) {
        // ---- topk role (one block per batch) ----
        __shared__ unsigned long long s_warp[THREADS / 32];
        __shared__ unsigned long long s_best;

        const int b    = bid - NCOLSUM;
        const int lane = t & 31;
        const int wid  = t >> 5;

        if (t == 0) {
            while (atomicAdd(&g_cnt[b], 0) < ROWCH * COLCH) __nanosleep(256);
        }
        __syncthreads();
        __threadfence();                      // acquire: see partials

        // Fused reduce of the 8 row-chunk partials into registers (L2-hot).
        float v[8];
        #pragma unroll
        for (int i = 0; i < 8; i++) {
            const int c = i * THREADS + t;
            float s = 0.f;
            #pragma unroll
            for (int rc = 0; rc < ROWCH; rc++)
                s += g_partials[((size_t)rc * B + b) * S + c];
            v[i] = s;
        }

        // 16x iterative argmax. Key packing -> descending value, lowest-index
        // tie-break: matches lax.top_k (index order feeds take_along_axis).
        for (int it = 0; it < TOPK; it++) {
            unsigned long long best = 0ull;
            #pragma unroll
            for (int i = 0; i < 8; i++) {
                unsigned fb = __float_as_uint(v[i]);
                fb = (fb & 0x80000000u) ? ~fb : (fb | 0x80000000u);
                unsigned long long key =
                    ((unsigned long long)fb << 32) |
                    (unsigned)(0xFFFFFFFFu - (unsigned)(i * THREADS + t));
                best = (key > best) ? key : best;
            }
            #pragma unroll
            for (int off = 16; off > 0; off >>= 1) {
                unsigned long long o = __shfl_xor_sync(0xFFFFFFFFu, best, off);
                best = (o > best) ? o : best;
            }
            if (lane == 0) s_warp[wid] = best;
            __syncthreads();
            if (t == 0) {
                unsigned long long m = s_warp[0];
                #pragma unroll
                for (int j = 1; j < THREADS / 32; j++)
                    m = (s_warp[j] > m) ? s_warp[j] : m;
                s_best = m;
                g_topk[b * TOPK + it] =
                    (int)(0xFFFFFFFFu - (unsigned)(m & 0xFFFFFFFFull));
            }
            __syncthreads();
            const int c = (int)(0xFFFFFFFFu - (unsigned)(s_best & 0xFFFFFFFFull));
            if ((c & (THREADS - 1)) == t)
                v[c >> 8] = -3.402823466e38f;
        }

        __threadfence();                      // release: g_topk before flag
        __syncthreads();
        if (t == 0) atomicExch(&g_flag[b], 1);

    } else {
        // ---- gather role (4 blocks per batch) ----
        __shared__ int s_idx[TOPK];

        const int g     = bid - (NCOLSUM + NTOPK);
        const int b     = g >> 2;
        const int fpart = g & 3;
        const int f     = fpart * THREADS + t;      // 0..F-1

        if (t == 0) {
            while (atomicAdd(&g_flag[b], 0) == 0) __nanosleep(256);
        }
        __syncthreads();
        __threadfence();                      // acquire: see g_topk
        if (t < TOPK) s_idx[t] = g_topk[b * TOPK + t];
        __syncthreads();

        const float* __restrict__ row = x + ((size_t)b * F + f) * S;

        float r[TOPK];
        #pragma unroll
        for (int k = 0; k < TOPK; k++)
            r[k] = __ldg(row + s_idx[k]);

        float4* __restrict__ o4 =
            reinterpret_cast<float4*>(out + ((size_t)b * F + f) * TOPK);
        #pragma unroll
        for (int j = 0; j < TOPK / 4; j++)
            o4[j] = make_float4(r[4 * j], r[4 * j + 1], r[4 * j + 2], r[4 * j + 3]);
    }
}

// ---------------------------------------------------------------------------
extern "C" void kernel_launch(void* const* d_in, const int* in_sizes, int n_in,
                              void* d_out, int out_size) {
    const float* x = (const float*)d_in[0];   // [B, F, S]
    const float* w = (const float*)d_in[1];   // [B, S, S]
    float* out = (float*)d_out;               // [B, F, TOPK]

    (void)in_sizes; (void)n_in; (void)out_size;

    reset_kernel<<<1, THREADS>>>();
    fused_kernel<<<NBLOCKS, THREADS>>>(x, w, out);
}